// round 15
// baseline (speedup 1.0000x reference)
#include <cuda_runtime.h>
#include <math.h>

// ---------------------------------------------------------------------------
// Weighted Kabsch, two-kernel split with PDL overlap.
// Kernel 1: pure streaming reduce (one CTA per batch, 512 threads, all 7
// LDG.128 per thread front-batched). Triggers dependent launch after storing
// its 16 sufficient statistics.
// Kernel 2: fp32 3x3 SVD chains (3 Jacobi sweeps), launched with
// programmatic dependent launch -> prologue overlaps the reduce tail;
// griddepcontrol.wait before reading g_sums.
// ---------------------------------------------------------------------------

#define MAX_B 2048
#define RED_THREADS 512

// [0] sum w | [1:4] sum w*src | [4:7] sum w*tgt | [7:16] sum w*tgt_i*src_j
__device__ float g_sums[MAX_B][16];

__global__ void __launch_bounds__(RED_THREADS)
reduce_kernel(const float* __restrict__ src,
              const float* __restrict__ tgt,
              const float* __restrict__ wts,
              int N)
{
    const int b = blockIdx.x;
    const float4* s4 = (const float4*)(src + (size_t)b * N * 3);
    const float4* t4 = (const float4*)(tgt + (size_t)b * N * 3);
    const float4* w4 = (const float4*)(wts + (size_t)b * N);

    float acc[16];
#pragma unroll
    for (int i = 0; i < 16; i++) acc[i] = 0.f;

    const int tid = threadIdx.x;
    const int ngroups = N >> 2;  // N divisible by 4

    for (int g = tid; g < ngroups; g += RED_THREADS) {
        float4 wv = w4[g];
        float4 a0 = s4[g * 3 + 0];
        float4 a1 = s4[g * 3 + 1];
        float4 a2 = s4[g * 3 + 2];
        float4 b0 = t4[g * 3 + 0];
        float4 b1 = t4[g * 3 + 1];
        float4 b2 = t4[g * 3 + 2];

        const float sx[4][3] = {{a0.x, a0.y, a0.z},
                                {a0.w, a1.x, a1.y},
                                {a1.z, a1.w, a2.x},
                                {a2.y, a2.z, a2.w}};
        const float tx[4][3] = {{b0.x, b0.y, b0.z},
                                {b0.w, b1.x, b1.y},
                                {b1.z, b1.w, b2.x},
                                {b2.y, b2.z, b2.w}};
        const float wa[4] = {wv.x, wv.y, wv.z, wv.w};

#pragma unroll
        for (int p = 0; p < 4; p++) {
            const float w = wa[p];
            const float s0 = sx[p][0], s1 = sx[p][1], s2 = sx[p][2];
            const float wt0 = w * tx[p][0];
            const float wt1 = w * tx[p][1];
            const float wt2 = w * tx[p][2];
            acc[0] += w;
            acc[1] += w * s0;  acc[2] += w * s1;  acc[3] += w * s2;
            acc[4] += wt0;     acc[5] += wt1;     acc[6] += wt2;
            acc[7]  += wt0 * s0;  acc[8]  += wt0 * s1;  acc[9]  += wt0 * s2;
            acc[10] += wt1 * s0;  acc[11] += wt1 * s1;  acc[12] += wt1 * s2;
            acc[13] += wt2 * s0;  acc[14] += wt2 * s1;  acc[15] += wt2 * s2;
        }
    }

    // warp reduce
#pragma unroll
    for (int i = 0; i < 16; i++) {
#pragma unroll
        for (int o = 16; o > 0; o >>= 1)
            acc[i] += __shfl_down_sync(0xffffffffu, acc[i], o);
    }

    __shared__ float smem[RED_THREADS / 32][16];
    const int warp = tid >> 5;
    const int lane = tid & 31;
    if (lane == 0) {
#pragma unroll
        for (int i = 0; i < 16; i++) smem[warp][i] = acc[i];
    }
    __syncthreads();

    if (tid < 16) {
        float v = 0.f;
#pragma unroll
        for (int w = 0; w < RED_THREADS / 32; w++) v += smem[w][tid];
        g_sums[b][tid] = v;
    }
    __syncthreads();

    // allow the dependent SVD grid to launch (its wait covers visibility)
    if (tid == 0)
        asm volatile("griddepcontrol.launch_dependents;");
}

// ---------------------------------------------------------------------------

__device__ __forceinline__ float det3f(const float m[3][3]) {
    return m[0][0] * (m[1][1] * m[2][2] - m[1][2] * m[2][1])
         - m[0][1] * (m[1][0] * m[2][2] - m[1][2] * m[2][0])
         + m[0][2] * (m[1][0] * m[2][1] - m[1][1] * m[2][0]);
}

// 32 threads per CTA, one batch per thread, 64 CTAs across SMs.
__global__ void __launch_bounds__(32)
svd_kernel(float* __restrict__ out, int B)
{
    const int b = blockIdx.x * 32 + threadIdx.x;

    // overlap prologue with reduce tail; block until reduce grid complete
    asm volatile("griddepcontrol.wait;" ::: "memory");

    if (b >= B) return;

    const float* s = g_sums[b];
    const float Sw = s[0];
    const float Sx[3] = {s[1], s[2], s[3]};
    const float Tx[3] = {s[4], s[5], s[6]};
    const float M[3][3] = {{s[7], s[8], s[9]},
                           {s[10], s[11], s[12]},
                           {s[13], s[14], s[15]}};

    const float w = Sw + 1e-4f;
    const float winv = __fdividef(1.0f, w);
    float sc[3], tc[3];
#pragma unroll
    for (int i = 0; i < 3; i++) { sc[i] = Sx[i] * winv; tc[i] = Tx[i] * winv; }

    float A[3][3];
#pragma unroll
    for (int i = 0; i < 3; i++)
#pragma unroll
        for (int j = 0; j < 3; j++)
            A[i][j] = (M[i][j] - tc[i] * Sx[j] - Tx[i] * sc[j] + Sw * tc[i] * sc[j]) * winv;

    float Bm[3][3];
#pragma unroll
    for (int i = 0; i < 3; i++)
#pragma unroll
        for (int j = 0; j < 3; j++)
            Bm[i][j] = A[0][i] * A[0][j] + A[1][i] * A[1][j] + A[2][i] * A[2][j];

    float V[3][3] = {{1, 0, 0}, {0, 1, 0}, {0, 0, 1}};

    // cyclic Jacobi, 3 sweeps (quadratic convergence: off-diag ~1e-7 rel)
#pragma unroll 1
    for (int sweep = 0; sweep < 3; sweep++) {
#pragma unroll
        for (int pair = 0; pair < 3; pair++) {
            const int p = (pair == 2) ? 1 : 0;
            const int q = (pair == 0) ? 1 : 2;
            const float apq = Bm[p][q];
            const float app = Bm[p][p], aqq = Bm[q][q];
            if (apq * apq <= 1e-22f * app * aqq + 1e-38f) continue;
            const float tau = __fdividef(aqq - app, 2.0f * apq);
            const float t = __fdividef((tau >= 0.0f) ? 1.0f : -1.0f,
                                       fabsf(tau) + sqrtf(1.0f + tau * tau));
            const float c = rsqrtf(1.0f + t * t);
            const float sn = t * c;
#pragma unroll
            for (int k = 0; k < 3; k++) {
                const float bkp = Bm[k][p], bkq = Bm[k][q];
                Bm[k][p] = c * bkp - sn * bkq;
                Bm[k][q] = sn * bkp + c * bkq;
            }
#pragma unroll
            for (int k = 0; k < 3; k++) {
                const float bpk = Bm[p][k], bqk = Bm[q][k];
                Bm[p][k] = c * bpk - sn * bqk;
                Bm[q][k] = sn * bpk + c * bqk;
            }
#pragma unroll
            for (int k = 0; k < 3; k++) {
                const float vkp = V[k][p], vkq = V[k][q];
                V[k][p] = c * vkp - sn * vkq;
                V[k][q] = sn * vkp + c * vkq;
            }
        }
    }

    float lam[3] = {Bm[0][0], Bm[1][1], Bm[2][2]};
#pragma unroll
    for (int i = 0; i < 2; i++)
#pragma unroll
        for (int j = 0; j < 2 - i; j++)
            if (lam[j] < lam[j + 1]) {
                float tl = lam[j]; lam[j] = lam[j + 1]; lam[j + 1] = tl;
#pragma unroll
                for (int k = 0; k < 3; k++) {
                    float tv = V[k][j]; V[k][j] = V[k][j + 1]; V[k][j + 1] = tv;
                }
            }

    float U[3][3];
    float norms[3];
#pragma unroll
    for (int k = 0; k < 3; k++) {
        float uv[3];
#pragma unroll
        for (int i = 0; i < 3; i++)
            uv[i] = A[i][0] * V[0][k] + A[i][1] * V[1][k] + A[i][2] * V[2][k];
        const float nsq = uv[0] * uv[0] + uv[1] * uv[1] + uv[2] * uv[2];
        norms[k] = sqrtf(nsq);
        const float inv = (nsq > 1e-36f) ? rsqrtf(nsq) : 0.0f;
#pragma unroll
        for (int i = 0; i < 3; i++) U[i][k] = uv[i] * inv;
    }
    if (norms[2] < 1e-7f * (norms[0] + 1e-30f)) {
        U[0][2] = U[1][0] * U[2][1] - U[2][0] * U[1][1];
        U[1][2] = U[2][0] * U[0][1] - U[0][0] * U[2][1];
        U[2][2] = U[0][0] * U[1][1] - U[1][0] * U[0][1];
    }

    const float d = det3f(U) * det3f(V);

    float R[3][3];
#pragma unroll
    for (int i = 0; i < 3; i++)
#pragma unroll
        for (int j = 0; j < 3; j++)
            R[i][j] = U[i][0] * V[j][0] + U[i][1] * V[j][1] + d * U[i][2] * V[j][2];

    float t1[3], t[3];
#pragma unroll
    for (int i = 0; i < 3; i++)
        t1[i] = sc[i] - (R[0][i] * tc[0] + R[1][i] * tc[1] + R[2][i] * tc[2]);
#pragma unroll
    for (int i = 0; i < 3; i++)
        t[i] = -(R[i][0] * t1[0] + R[i][1] * t1[1] + R[i][2] * t1[2]);

    float* Rout = out + (size_t)b * 9;
    float* Tout = out + (size_t)B * 9 + (size_t)b * 3;
#pragma unroll
    for (int i = 0; i < 3; i++)
#pragma unroll
        for (int j = 0; j < 3; j++)
            Rout[i * 3 + j] = R[i][j];
#pragma unroll
    for (int i = 0; i < 3; i++) Tout[i] = t[i];
}

// ---------------------------------------------------------------------------

extern "C" void kernel_launch(void* const* d_in, const int* in_sizes, int n_in,
                              void* d_out, int out_size)
{
    const float* src = (const float*)d_in[0];
    const float* tgt = (const float*)d_in[1];
    const float* wts = (const float*)d_in[2];
    float* out = (float*)d_out;

    const int B = out_size / 12;            // 9 (R) + 3 (t) per batch
    const int N = in_sizes[2] / B;          // weights are (B,1,N)

    reduce_kernel<<<B, RED_THREADS>>>(src, tgt, wts, N);

    // SVD kernel with programmatic dependent launch -> overlaps reduce tail
    cudaLaunchConfig_t cfg = {};
    cfg.gridDim = dim3((B + 31) / 32, 1, 1);
    cfg.blockDim = dim3(32, 1, 1);
    cudaLaunchAttribute attrs[1];
    attrs[0].id = cudaLaunchAttributeProgrammaticStreamSerialization;
    attrs[0].val.programmaticStreamSerializationAllowed = 1;
    cfg.attrs = attrs;
    cfg.numAttrs = 1;
    cudaLaunchKernelEx(&cfg, svd_kernel, out, B);
}

// round 16
// speedup vs baseline: 1.0548x; 1.0548x over previous
#include <cuda_runtime.h>
#include <math.h>

// ---------------------------------------------------------------------------
// Weighted Kabsch, two-kernel split with PDL overlap.
// Kernel 1: pure streaming reduce (one CTA per batch, 256 threads — the best
// measured streamer at ~5.3 TB/s).
// Kernel 2: fp32 3x3 SVD chains, BRANCHLESS Jacobi (selp-guarded rotations,
// no convergence-skip divergence -> lanes stay converged), PDL-launched so
// its prologue overlaps the reduce tail.
// ---------------------------------------------------------------------------

#define MAX_B 2048
#define RED_THREADS 256

// [0] sum w | [1:4] sum w*src | [4:7] sum w*tgt | [7:16] sum w*tgt_i*src_j
__device__ float g_sums[MAX_B][16];

__global__ void __launch_bounds__(RED_THREADS)
reduce_kernel(const float* __restrict__ src,
              const float* __restrict__ tgt,
              const float* __restrict__ wts,
              int N)
{
    const int b = blockIdx.x;
    const float4* s4 = (const float4*)(src + (size_t)b * N * 3);
    const float4* t4 = (const float4*)(tgt + (size_t)b * N * 3);
    const float4* w4 = (const float4*)(wts + (size_t)b * N);

    float acc[16];
#pragma unroll
    for (int i = 0; i < 16; i++) acc[i] = 0.f;

    const int tid = threadIdx.x;
    const int ngroups = N >> 2;  // N divisible by 4

    for (int g = tid; g < ngroups; g += RED_THREADS) {
        float4 wv = w4[g];
        float4 a0 = s4[g * 3 + 0];
        float4 a1 = s4[g * 3 + 1];
        float4 a2 = s4[g * 3 + 2];
        float4 b0 = t4[g * 3 + 0];
        float4 b1 = t4[g * 3 + 1];
        float4 b2 = t4[g * 3 + 2];

        const float sx[4][3] = {{a0.x, a0.y, a0.z},
                                {a0.w, a1.x, a1.y},
                                {a1.z, a1.w, a2.x},
                                {a2.y, a2.z, a2.w}};
        const float tx[4][3] = {{b0.x, b0.y, b0.z},
                                {b0.w, b1.x, b1.y},
                                {b1.z, b1.w, b2.x},
                                {b2.y, b2.z, b2.w}};
        const float wa[4] = {wv.x, wv.y, wv.z, wv.w};

#pragma unroll
        for (int p = 0; p < 4; p++) {
            const float w = wa[p];
            const float s0 = sx[p][0], s1 = sx[p][1], s2 = sx[p][2];
            const float wt0 = w * tx[p][0];
            const float wt1 = w * tx[p][1];
            const float wt2 = w * tx[p][2];
            acc[0] += w;
            acc[1] += w * s0;  acc[2] += w * s1;  acc[3] += w * s2;
            acc[4] += wt0;     acc[5] += wt1;     acc[6] += wt2;
            acc[7]  += wt0 * s0;  acc[8]  += wt0 * s1;  acc[9]  += wt0 * s2;
            acc[10] += wt1 * s0;  acc[11] += wt1 * s1;  acc[12] += wt1 * s2;
            acc[13] += wt2 * s0;  acc[14] += wt2 * s1;  acc[15] += wt2 * s2;
        }
    }

    // warp reduce
#pragma unroll
    for (int i = 0; i < 16; i++) {
#pragma unroll
        for (int o = 16; o > 0; o >>= 1)
            acc[i] += __shfl_down_sync(0xffffffffu, acc[i], o);
    }

    __shared__ float smem[RED_THREADS / 32][16];
    const int warp = tid >> 5;
    const int lane = tid & 31;
    if (lane == 0) {
#pragma unroll
        for (int i = 0; i < 16; i++) smem[warp][i] = acc[i];
    }
    __syncthreads();

    if (tid < 16) {
        float v = 0.f;
#pragma unroll
        for (int w = 0; w < RED_THREADS / 32; w++) v += smem[w][tid];
        g_sums[b][tid] = v;
    }
    __syncthreads();

    if (tid == 0)
        asm volatile("griddepcontrol.launch_dependents;");
}

// ---------------------------------------------------------------------------

__device__ __forceinline__ float det3f(const float m[3][3]) {
    return m[0][0] * (m[1][1] * m[2][2] - m[1][2] * m[2][1])
         - m[0][1] * (m[1][0] * m[2][2] - m[1][2] * m[2][0])
         + m[0][2] * (m[1][0] * m[2][1] - m[1][1] * m[2][0]);
}

// 32 threads per CTA, one batch per thread, 64 CTAs across SMs.
__global__ void __launch_bounds__(32)
svd_kernel(float* __restrict__ out, int B)
{
    const int b = blockIdx.x * 32 + threadIdx.x;

    asm volatile("griddepcontrol.wait;" ::: "memory");

    if (b >= B) return;

    const float* s = g_sums[b];
    const float Sw = s[0];
    const float Sx[3] = {s[1], s[2], s[3]};
    const float Tx[3] = {s[4], s[5], s[6]};
    const float M[3][3] = {{s[7], s[8], s[9]},
                           {s[10], s[11], s[12]},
                           {s[13], s[14], s[15]}};

    const float w = Sw + 1e-4f;
    const float winv = __fdividef(1.0f, w);
    float sc[3], tc[3];
#pragma unroll
    for (int i = 0; i < 3; i++) { sc[i] = Sx[i] * winv; tc[i] = Tx[i] * winv; }

    float A[3][3];
#pragma unroll
    for (int i = 0; i < 3; i++)
#pragma unroll
        for (int j = 0; j < 3; j++)
            A[i][j] = (M[i][j] - tc[i] * Sx[j] - Tx[i] * sc[j] + Sw * tc[i] * sc[j]) * winv;

    float Bm[3][3];
#pragma unroll
    for (int i = 0; i < 3; i++)
#pragma unroll
        for (int j = 0; j < 3; j++)
            Bm[i][j] = A[0][i] * A[0][j] + A[1][i] * A[1][j] + A[2][i] * A[2][j];

    float V[3][3] = {{1, 0, 0}, {0, 1, 0}, {0, 0, 1}};

    // cyclic Jacobi, 3 sweeps, BRANCHLESS rotations (no lane divergence):
    // when |apq| is negligible the rotation angle is forced to 0 via selp,
    // making it an identity rotation instead of a divergent skip.
#pragma unroll 1
    for (int sweep = 0; sweep < 3; sweep++) {
#pragma unroll
        for (int pair = 0; pair < 3; pair++) {
            const int p = (pair == 2) ? 1 : 0;
            const int q = (pair == 0) ? 1 : 2;
            const float apq = Bm[p][q];
            const float app = Bm[p][p], aqq = Bm[q][q];
            const bool live = (apq * apq > 1e-22f * app * aqq + 1e-38f);
            const float apq_safe = live ? apq : 1.0f;          // selp
            const float tau = __fdividef(aqq - app, 2.0f * apq_safe);
            float t = __fdividef((tau >= 0.0f) ? 1.0f : -1.0f,
                                 fabsf(tau) + sqrtf(1.0f + tau * tau));
            t = live ? t : 0.0f;                               // selp -> identity
            const float c = rsqrtf(1.0f + t * t);
            const float sn = t * c;
#pragma unroll
            for (int k = 0; k < 3; k++) {
                const float bkp = Bm[k][p], bkq = Bm[k][q];
                Bm[k][p] = c * bkp - sn * bkq;
                Bm[k][q] = sn * bkp + c * bkq;
            }
#pragma unroll
            for (int k = 0; k < 3; k++) {
                const float bpk = Bm[p][k], bqk = Bm[q][k];
                Bm[p][k] = c * bpk - sn * bqk;
                Bm[q][k] = sn * bpk + c * bqk;
            }
#pragma unroll
            for (int k = 0; k < 3; k++) {
                const float vkp = V[k][p], vkq = V[k][q];
                V[k][p] = c * vkp - sn * vkq;
                V[k][q] = sn * vkp + c * vkq;
            }
        }
    }

    float lam[3] = {Bm[0][0], Bm[1][1], Bm[2][2]};
    // branchless descending sort of (lam, V columns)
#pragma unroll
    for (int i = 0; i < 2; i++)
#pragma unroll
        for (int j = 0; j < 2 - i; j++) {
            const bool sw = lam[j] < lam[j + 1];
            const float l0 = lam[j], l1 = lam[j + 1];
            lam[j] = sw ? l1 : l0;
            lam[j + 1] = sw ? l0 : l1;
#pragma unroll
            for (int k = 0; k < 3; k++) {
                const float v0 = V[k][j], v1 = V[k][j + 1];
                V[k][j] = sw ? v1 : v0;
                V[k][j + 1] = sw ? v0 : v1;
            }
        }

    float U[3][3];
    float norms[3];
#pragma unroll
    for (int k = 0; k < 3; k++) {
        float uv[3];
#pragma unroll
        for (int i = 0; i < 3; i++)
            uv[i] = A[i][0] * V[0][k] + A[i][1] * V[1][k] + A[i][2] * V[2][k];
        const float nsq = uv[0] * uv[0] + uv[1] * uv[1] + uv[2] * uv[2];
        norms[k] = sqrtf(nsq);
        const float inv = (nsq > 1e-36f) ? rsqrtf(nsq) : 0.0f;
#pragma unroll
        for (int i = 0; i < 3; i++) U[i][k] = uv[i] * inv;
    }
    // degenerate smallest singular value -> complete right-handed frame
    // (branchless: select between computed column and cross product)
    {
        const bool degen = norms[2] < 1e-7f * (norms[0] + 1e-30f);
        const float cx = U[1][0] * U[2][1] - U[2][0] * U[1][1];
        const float cy = U[2][0] * U[0][1] - U[0][0] * U[2][1];
        const float cz = U[0][0] * U[1][1] - U[1][0] * U[0][1];
        U[0][2] = degen ? cx : U[0][2];
        U[1][2] = degen ? cy : U[1][2];
        U[2][2] = degen ? cz : U[2][2];
    }

    const float d = det3f(U) * det3f(V);

    float R[3][3];
#pragma unroll
    for (int i = 0; i < 3; i++)
#pragma unroll
        for (int j = 0; j < 3; j++)
            R[i][j] = U[i][0] * V[j][0] + U[i][1] * V[j][1] + d * U[i][2] * V[j][2];

    float t1[3], t[3];
#pragma unroll
    for (int i = 0; i < 3; i++)
        t1[i] = sc[i] - (R[0][i] * tc[0] + R[1][i] * tc[1] + R[2][i] * tc[2]);
#pragma unroll
    for (int i = 0; i < 3; i++)
        t[i] = -(R[i][0] * t1[0] + R[i][1] * t1[1] + R[i][2] * t1[2]);

    float* Rout = out + (size_t)b * 9;
    float* Tout = out + (size_t)B * 9 + (size_t)b * 3;
#pragma unroll
    for (int i = 0; i < 3; i++)
#pragma unroll
        for (int j = 0; j < 3; j++)
            Rout[i * 3 + j] = R[i][j];
#pragma unroll
    for (int i = 0; i < 3; i++) Tout[i] = t[i];
}

// ---------------------------------------------------------------------------

extern "C" void kernel_launch(void* const* d_in, const int* in_sizes, int n_in,
                              void* d_out, int out_size)
{
    const float* src = (const float*)d_in[0];
    const float* tgt = (const float*)d_in[1];
    const float* wts = (const float*)d_in[2];
    float* out = (float*)d_out;

    const int B = out_size / 12;            // 9 (R) + 3 (t) per batch
    const int N = in_sizes[2] / B;          // weights are (B,1,N)

    reduce_kernel<<<B, RED_THREADS>>>(src, tgt, wts, N);

    cudaLaunchConfig_t cfg = {};
    cfg.gridDim = dim3((B + 31) / 32, 1, 1);
    cfg.blockDim = dim3(32, 1, 1);
    cudaLaunchAttribute attrs[1];
    attrs[0].id = cudaLaunchAttributeProgrammaticStreamSerialization;
    attrs[0].val.programmaticStreamSerializationAllowed = 1;
    cfg.attrs = attrs;
    cfg.numAttrs = 1;
    cudaLaunchKernelEx(&cfg, svd_kernel, out, B);
}